// round 12
// baseline (speedup 1.0000x reference)
#include <cuda_runtime.h>
#include <cuda_bf16.h>
#include <math.h>

#define NP 64
#define NR 8
#define NK 500
#define H 256
#define HEADS 8
#define VD 8
#define HD 32
#define BB (NP*NR)          // 512
#define NEGINF (__int_as_float(0xff800000))

// ---------------- scratch (device globals; no allocations allowed) ----------------
__device__ float g_gates [BB * 4 * H];    // 512 x 1024 (partial 0: query@Wih)
__device__ float g_gates2[BB * 4 * H];    // 512 x 1024 (partial 1: state1@Whh)
__device__ float g_xcat [BB * H];         // 512 x 256
__device__ float g_qp0  [BB * H];         // Q-proj k-split partials
__device__ float g_qp1  [BB * H];
__device__ float g_qp2  [BB * H];
__device__ float g_qp3  [BB * H];
__device__ float g_S    [HEADS * NP * NR * NK];  // softmax probs, 8MB
__device__ float g_qm0  [BB * H];         // qm k-split partials
__device__ float g_qm1  [BB * H];
__device__ float g_qm2  [BB * H];
__device__ float g_qm3  [BB * H];
__device__ float g_logit[BB * NK];        // 512 x 500

__device__ __forceinline__ float tanha(float x) {
    float y; asm("tanh.approx.f32 %0, %1;" : "=f"(y) : "f"(x)); return y;
}
__device__ __forceinline__ float sigm(float x) { return 1.0f / (1.0f + __expf(-x)); }

// =====================================================================
// Kernel 1: split-K gates GEMM. z=0: query@Wih^T, z=1: state1@Whh^T
// 64M x 128N tiles, 4x8 micro (32 FMA / 3 LDS.128), grid (8,8,2)=128.
// =====================================================================
__global__ __launch_bounds__(256)
void k_gates(const float* __restrict__ q, const float* __restrict__ s1,
             const float* __restrict__ Wih, const float* __restrict__ Whh)
{
    __shared__ float As[2][16][68];
    __shared__ float Bs[2][16][132];
    const int t  = threadIdx.x;
    const int tx = t & 15, ty = t >> 4;
    const int n0 = blockIdx.x * 128;
    const int m0 = blockIdx.y * 64;
    const int z  = blockIdx.z;
    const float* Ap = z ? s1  : q;
    const float* Wp = z ? Whh : Wih;

    float acc[4][8] = {};

    auto fetchA = [&](int kt, int r, float& a) {        // r < 4
        int i = r * 256 + t;
        int mm = i >> 4, kx = i & 15;
        a = Ap[(m0 + mm) * 256 + kt * 16 + kx];
    };
    auto fetchB = [&](int kt, int r, float& b) {        // r < 8
        int i = r * 256 + t;
        int nn = i >> 4, kx = i & 15;
        b = Wp[(n0 + nn) * 256 + kt * 16 + kx];
    };

    // preload tile 0
    #pragma unroll
    for (int r = 0; r < 4; r++) {
        float a; fetchA(0, r, a);
        int i = r * 256 + t;
        As[0][i & 15][i >> 4] = a;
    }
    #pragma unroll
    for (int r = 0; r < 8; r++) {
        float b; fetchB(0, r, b);
        int i = r * 256 + t;
        Bs[0][i & 15][i >> 4] = b;
    }
    __syncthreads();

    int cur = 0;
    for (int kt = 0; kt < 16; kt++) {
        float pa[4], pb[8];
        if (kt < 15) {
            #pragma unroll
            for (int r = 0; r < 4; r++) fetchA(kt + 1, r, pa[r]);
            #pragma unroll
            for (int r = 0; r < 8; r++) fetchB(kt + 1, r, pb[r]);
        }
        #pragma unroll
        for (int k = 0; k < 16; k++) {
            float4 a4 = *(const float4*)&As[cur][k][ty * 4];
            float4 b0 = *(const float4*)&Bs[cur][k][tx * 4];
            float4 b1 = *(const float4*)&Bs[cur][k][64 + tx * 4];
            float av[4] = {a4.x, a4.y, a4.z, a4.w};
            float bv[8] = {b0.x, b0.y, b0.z, b0.w, b1.x, b1.y, b1.z, b1.w};
            #pragma unroll
            for (int r = 0; r < 4; r++)
                #pragma unroll
                for (int c = 0; c < 8; c++)
                    acc[r][c] = fmaf(av[r], bv[c], acc[r][c]);
        }
        if (kt < 15) {
            int nxt = cur ^ 1;
            #pragma unroll
            for (int r = 0; r < 4; r++) {
                int i = r * 256 + t;
                As[nxt][i & 15][i >> 4] = pa[r];
            }
            #pragma unroll
            for (int r = 0; r < 8; r++) {
                int i = r * 256 + t;
                Bs[nxt][i & 15][i >> 4] = pb[r];
            }
            __syncthreads();
            cur = nxt;
        }
    }
    float* dst = z ? g_gates2 : g_gates;
    #pragma unroll
    for (int r = 0; r < 4; r++) {
        int m = m0 + ty * 4 + r;
        float4 o0 = {acc[r][0], acc[r][1], acc[r][2], acc[r][3]};
        float4 o1 = {acc[r][4], acc[r][5], acc[r][6], acc[r][7]};
        *(float4*)&dst[m * 1024 + n0 + tx * 4]      = o0;
        *(float4*)&dst[m * 1024 + n0 + 64 + tx * 4] = o1;
    }
}

// =====================================================================
// Kernel 2a/2b: LSTM activations
// =====================================================================
__global__ __launch_bounds__(256)
void k_act_c(const float* __restrict__ s2,
             const float* __restrict__ bih, const float* __restrict__ bhh,
             float* __restrict__ out)
{
    int idx4 = blockIdx.x * 256 + threadIdx.x;
    int b = idx4 >> 6, j4 = (idx4 & 63);
    const float4* g0 = (const float4*)(g_gates  + b * 1024);
    const float4* g1 = (const float4*)(g_gates2 + b * 1024);
    const float4* B0 = (const float4*)bih;
    const float4* B1 = (const float4*)bhh;

    float4 gi = g0[j4],      gf = g0[j4 + 64],  gg = g0[j4 + 128];
    float4 hi = g1[j4],      hf = g1[j4 + 64],  hg = g1[j4 + 128];
    float4 bi = B0[j4],      bf = B0[j4 + 64],  bg = B0[j4 + 128];
    float4 ci = B1[j4],      cf = B1[j4 + 64],  cg_ = B1[j4 + 128];
    float4 s4 = ((const float4*)s2)[idx4];

    float iv[4] = {gi.x+hi.x+bi.x+ci.x, gi.y+hi.y+bi.y+ci.y, gi.z+hi.z+bi.z+ci.z, gi.w+hi.w+bi.w+ci.w};
    float fv[4] = {gf.x+hf.x+bf.x+cf.x, gf.y+hf.y+bf.y+cf.y, gf.z+hf.z+bf.z+cf.z, gf.w+hf.w+bf.w+cf.w};
    float gv[4] = {gg.x+hg.x+bg.x+cg_.x, gg.y+hg.y+bg.y+cg_.y, gg.z+hg.z+bg.z+cg_.z, gg.w+hg.w+bg.w+cg_.w};
    float sv[4] = {s4.x, s4.y, s4.z, s4.w};

    float4 cout; float* cp = (float*)&cout;
    #pragma unroll
    for (int e = 0; e < 4; e++)
        cp[e] = sigm(fv[e]) * sv[e] + sigm(iv[e]) * tanhf(gv[e]);
    ((float4*)out)[BB * H / 4 + idx4] = cout;
}

__global__ __launch_bounds__(256)
void k_act_h(const float* __restrict__ bih, const float* __restrict__ bhh,
             float* __restrict__ out)
{
    int idx4 = blockIdx.x * 256 + threadIdx.x;
    int b = idx4 >> 6, j4 = (idx4 & 63);
    const float4* g0 = (const float4*)(g_gates  + b * 1024);
    const float4* g1 = (const float4*)(g_gates2 + b * 1024);

    float4 go = g0[j4 + 192];
    float4 ho = g1[j4 + 192];
    float4 bo = ((const float4*)bih)[j4 + 192];
    float4 co = ((const float4*)bhh)[j4 + 192];
    float4 c4 = ((const float4*)out)[BB * H / 4 + idx4];

    float ov[4] = {go.x+ho.x+bo.x+co.x, go.y+ho.y+bo.y+co.y, go.z+ho.z+bo.z+co.z, go.w+ho.w+bo.w+co.w};
    float cv[4] = {c4.x, c4.y, c4.z, c4.w};

    float4 hout; float* hp = (float*)&hout;
    #pragma unroll
    for (int e = 0; e < 4; e++)
        hp[e] = sigm(ov[e]) * tanhf(cv[e]);
    ((float4*)out)[idx4] = hout;
}

// =====================================================================
// Kernel 3: Q projection GEMM (512x256 @ 256x256), split-K 4.
// =====================================================================
__global__ __launch_bounds__(256)
void k_qproj(const float* __restrict__ hbuf, const float* __restrict__ nnQ)
{
    __shared__ float As[2][16][68];
    __shared__ float Bs[2][16][68];
    const int t  = threadIdx.x;
    const int tx = t & 15, ty = t >> 4;
    const int n0 = blockIdx.x * 64;
    const int m0 = blockIdx.y * 64;
    const int kb = blockIdx.z * 64;

    float acc[4][4] = {};

    auto fetchA = [&](int kt, int r, float& a) {
        int i = r * 256 + t;
        int mm = i >> 4, kx = i & 15;
        a = hbuf[(m0 + mm) * 256 + kb + kt * 16 + kx];
    };
    auto fetchB = [&](int kt, int r, float& b) {
        int i = r * 256 + t;
        int kx = i >> 6, nn = i & 63;
        int n = n0 + nn;
        b = nnQ[(n >> 5) * (H * HD) + (kb + kt * 16 + kx) * HD + (n & 31)];
    };

    #pragma unroll
    for (int r = 0; r < 4; r++) {
        float a, b; fetchA(0, r, a); fetchB(0, r, b);
        int i = r * 256 + t;
        As[0][i & 15][i >> 4] = a;
        Bs[0][i >> 6][i & 63] = b;
    }
    __syncthreads();

    int cur = 0;
    #pragma unroll
    for (int kt = 0; kt < 4; kt++) {
        float pa[4], pb[4];
        if (kt < 3) {
            #pragma unroll
            for (int r = 0; r < 4; r++) { fetchA(kt + 1, r, pa[r]); fetchB(kt + 1, r, pb[r]); }
        }
        #pragma unroll
        for (int k = 0; k < 16; k++) {
            float4 a4 = *(const float4*)&As[cur][k][ty * 4];
            float4 b4 = *(const float4*)&Bs[cur][k][tx * 4];
            float av[4] = {a4.x, a4.y, a4.z, a4.w};
            float bv[4] = {b4.x, b4.y, b4.z, b4.w};
            #pragma unroll
            for (int r = 0; r < 4; r++)
                #pragma unroll
                for (int c = 0; c < 4; c++)
                    acc[r][c] = fmaf(av[r], bv[c], acc[r][c]);
        }
        if (kt < 3) {
            int nxt = cur ^ 1;
            #pragma unroll
            for (int r = 0; r < 4; r++) {
                int i = r * 256 + t;
                As[nxt][i & 15][i >> 4] = pa[r];
                Bs[nxt][i >> 6][i & 63] = pb[r];
            }
            __syncthreads();
            cur = nxt;
        }
    }
    float* dst = (blockIdx.z == 0) ? g_qp0 : (blockIdx.z == 1) ? g_qp1
               : (blockIdx.z == 2) ? g_qp2 : g_qp3;
    #pragma unroll
    for (int r = 0; r < 4; r++) {
        int m = m0 + ty * 4 + r;
        #pragma unroll
        for (int c = 0; c < 4; c++)
            dst[m * 256 + n0 + tx * 4 + c] = acc[r][c];
    }
}

// =====================================================================
// Kernel 4: scores + softmax per (p, head). Writes probs to g_S.
// =====================================================================
struct SmemScore {
    float Qs[8][32];
    float Ss[8][512];
};

__global__ __launch_bounds__(256)
void k_score(const float* __restrict__ K, const int* __restrict__ mask)
{
    __shared__ SmemScore sm;
    const int p = blockIdx.x, a = blockIdx.y;
    const int t = threadIdx.x, w = t >> 5, l = t & 31;

    {
        int i = (p * NR + w) * 256 + a * HD + l;
        sm.Qs[w][l] = (g_qp0[i] + g_qp1[i] + g_qp2[i] + g_qp3[i]) * 0.17677669529663687f;
    }
    __syncthreads();

    const float* Kp = K + (size_t)(a * NP + p) * NK * HD;
    #pragma unroll
    for (int sweep = 0; sweep < 2; sweep++) {
        int k = sweep * 256 + t;
        if (k < NK) {
            float4 kr[8];
            const float4* kp4 = (const float4*)(Kp + k * HD);
            #pragma unroll
            for (int i = 0; i < 8; i++) kr[i] = kp4[i];
            #pragma unroll
            for (int q = 0; q < 8; q++) {
                const float4* q4 = (const float4*)sm.Qs[q];
                float acc = 0.f;
                #pragma unroll
                for (int i = 0; i < 8; i++) {
                    float4 qq = q4[i];
                    acc = fmaf(kr[i].x, qq.x, acc);
                    acc = fmaf(kr[i].y, qq.y, acc);
                    acc = fmaf(kr[i].z, qq.z, acc);
                    acc = fmaf(kr[i].w, qq.w, acc);
                }
                int m = mask[(p * NR + q) * NK + k];
                sm.Ss[q][k] = m ? NEGINF : acc;
            }
        }
    }
    __syncthreads();

    {
        float mx = NEGINF;
        for (int k = l; k < NK; k += 32) mx = fmaxf(mx, sm.Ss[w][k]);
        #pragma unroll
        for (int o = 16; o; o >>= 1) mx = fmaxf(mx, __shfl_xor_sync(~0u, mx, o));
        float sum = 0.f;
        for (int k = l; k < NK; k += 32) {
            float e = __expf(sm.Ss[w][k] - mx);
            sm.Ss[w][k] = e; sum += e;
        }
        #pragma unroll
        for (int o = 16; o; o >>= 1) sum += __shfl_xor_sync(~0u, sum, o);
        float inv = 1.f / sum;
        float* Sp = g_S + ((size_t)(a * NP + p) * NR + w) * NK;
        for (int k = l; k < NK; k += 32) Sp[k] = sm.Ss[w][k] * inv;
    }
}

// =====================================================================
// Kernel 5: x = S @ V per (p, head).
// =====================================================================
struct SmemAV {
    alignas(16) float xp[4][8][32];
    float Ss[8][504];
};

__global__ __launch_bounds__(256)
void k_av(const float* __restrict__ V)
{
    __shared__ SmemAV sm;
    const int p = blockIdx.x, a = blockIdx.y;
    const int t = threadIdx.x, w = t >> 5, l = t & 31;

    {
        const float* Sp = g_S + ((size_t)(a * NP + p) * NR + w) * NK;
        for (int k = l; k < NK; k += 32) sm.Ss[w][k] = Sp[k];
    }
    __syncthreads();

    const int q  = w;
    const int dg = l & 7;
    const int ks = l >> 3;
    const float4* Vp4 = (const float4*)(V + (size_t)(a * NP + p) * NK * HD);

    float4 acc = {0.f, 0.f, 0.f, 0.f};
    const int kbase = ks * 125;
    #pragma unroll 5
    for (int kk = 0; kk < 125; kk++) {
        int k = kbase + kk;
        float sv = sm.Ss[q][k];
        float4 v = Vp4[k * 8 + dg];
        acc.x = fmaf(sv, v.x, acc.x);
        acc.y = fmaf(sv, v.y, acc.y);
        acc.z = fmaf(sv, v.z, acc.z);
        acc.w = fmaf(sv, v.w, acc.w);
    }
    *(float4*)&sm.xp[ks][q][dg * 4] = acc;
    __syncthreads();

    {
        int q2 = t >> 5, d = t & 31;
        float s = sm.xp[0][q2][d] + sm.xp[1][q2][d] + sm.xp[2][q2][d] + sm.xp[3][q2][d];
        g_xcat[(p * NR + q2) * H + a * HD + d] = s;
    }
}

// =====================================================================
// Kernel 6: qm = x_cat @ nn_O, tiled GEMM, split-K 4.
// =====================================================================
__global__ __launch_bounds__(256)
void k_qm(const float* __restrict__ nnO)
{
    __shared__ float As[2][16][68];
    __shared__ float Bs[2][16][68];
    const int t  = threadIdx.x;
    const int tx = t & 15, ty = t >> 4;
    const int n0 = blockIdx.x * 64;
    const int m0 = blockIdx.y * 64;
    const int kb = blockIdx.z * 64;

    float acc[4][4] = {};

    auto fetchA = [&](int kt, int r, float& a) {
        int i = r * 256 + t;
        int mm = i >> 4, kx = i & 15;
        a = g_xcat[(m0 + mm) * 256 + kb + kt * 16 + kx];
    };
    auto fetchB = [&](int kt, int r, float& b) {
        int i = r * 256 + t;
        int kx = i >> 6, nn = i & 63;
        b = nnO[(kb + kt * 16 + kx) * 256 + n0 + nn];
    };

    #pragma unroll
    for (int r = 0; r < 4; r++) {
        float a, b; fetchA(0, r, a); fetchB(0, r, b);
        int i = r * 256 + t;
        As[0][i & 15][i >> 4] = a;
        Bs[0][i >> 6][i & 63] = b;
    }
    __syncthreads();

    int cur = 0;
    #pragma unroll
    for (int kt = 0; kt < 4; kt++) {
        float pa[4], pb[4];
        if (kt < 3) {
            #pragma unroll
            for (int r = 0; r < 4; r++) { fetchA(kt + 1, r, pa[r]); fetchB(kt + 1, r, pb[r]); }
        }
        #pragma unroll
        for (int k = 0; k < 16; k++) {
            float4 a4 = *(const float4*)&As[cur][k][ty * 4];
            float4 b4 = *(const float4*)&Bs[cur][k][tx * 4];
            float av[4] = {a4.x, a4.y, a4.z, a4.w};
            float bv[4] = {b4.x, b4.y, b4.z, b4.w};
            #pragma unroll
            for (int r = 0; r < 4; r++)
                #pragma unroll
                for (int c = 0; c < 4; c++)
                    acc[r][c] = fmaf(av[r], bv[c], acc[r][c]);
        }
        if (kt < 3) {
            int nxt = cur ^ 1;
            #pragma unroll
            for (int r = 0; r < 4; r++) {
                int i = r * 256 + t;
                As[nxt][i & 15][i >> 4] = pa[r];
                Bs[nxt][i >> 6][i & 63] = pb[r];
            }
            __syncthreads();
            cur = nxt;
        }
    }
    float* dst = (blockIdx.z == 0) ? g_qm0 : (blockIdx.z == 1) ? g_qm1
               : (blockIdx.z == 2) ? g_qm2 : g_qm3;
    #pragma unroll
    for (int r = 0; r < 4; r++) {
        int m = m0 + ty * 4 + r;
        #pragma unroll
        for (int c = 0; c < 4; c++)
            dst[m * 256 + n0 + tx * 4 + c] = acc[r][c];
    }
}

// =====================================================================
// Kernel 7: logits, float4 lane mapping: lane l owns h = {4l..4l+3, 128+4l..+3}
// =====================================================================
__global__ __launch_bounds__(256)
void k_logit(const float* __restrict__ X, const float* __restrict__ varfeat,
             const float* __restrict__ nnA, const float* __restrict__ nnB,
             const float* __restrict__ nnW, const int* __restrict__ mask)
{
    __shared__ float qs[8][256];
    const int p = blockIdx.y, kt = blockIdx.x;
    const int t = threadIdx.x, w = t >> 5, l = t & 31;
    {
        const float4* q0 = (const float4*)(g_qm0 + p * 2048);
        const float4* q1 = (const float4*)(g_qm1 + p * 2048);
        const float4* q2 = (const float4*)(g_qm2 + p * 2048);
        const float4* q3 = (const float4*)(g_qm3 + p * 2048);
        float4* qsv = (float4*)qs;
        for (int i = t; i < 512; i += 256) {
            float4 a = q0[i], b = q1[i], c = q2[i], d = q3[i];
            qsv[i] = make_float4(a.x+b.x+c.x+d.x, a.y+b.y+c.y+d.y,
                                 a.z+b.z+c.z+d.z, a.w+b.w+c.w+d.w);
        }
    }

    float4 A4[2][8], W4[2], B4[2];
    #pragma unroll
    for (int j = 0; j < 2; j++) {
        W4[j] = *(const float4*)&nnW[j * 128 + l * 4];
        B4[j] = *(const float4*)&nnB[j * 128 + l * 4];
        #pragma unroll
        for (int v = 0; v < 8; v++)
            A4[j][v] = *(const float4*)&nnA[v * 256 + j * 128 + l * 4];
    }
    __syncthreads();

    const bool h16 = (l & 16), h8 = (l & 8), h4 = (l & 4);
    const int myq = (h16 ? 4 : 0) | (h8 ? 2 : 0) | (h4 ? 1 : 0);

    for (int it = 0; it < 8; it++) {
        int k = kt * 64 + it * 8 + w;
        if (k >= NK) continue;
        float vv[8];
        #pragma unroll
        for (int v = 0; v < 8; v++) vv[v] = __ldg(&varfeat[(p * VD + v) * NK + k]);
        const float4* Xp4 = (const float4*)(X + ((size_t)p * NK + k) * H);
        float4 base4[2];
        #pragma unroll
        for (int j = 0; j < 2; j++) {
            float4 x = Xp4[j * 32 + l];
            float4 b;
            b.x = x.x + B4[j].x; b.y = x.y + B4[j].y;
            b.z = x.z + B4[j].z; b.w = x.w + B4[j].w;
            #pragma unroll
            for (int v = 0; v < 8; v++) {
                b.x = fmaf(vv[v], A4[j][v].x, b.x);
                b.y = fmaf(vv[v], A4[j][v].y, b.y);
                b.z = fmaf(vv[v], A4[j][v].z, b.z);
                b.w = fmaf(vv[v], A4[j][v].w, b.w);
            }
            base4[j] = b;
        }
        float a8[8];
        #pragma unroll
        for (int q = 0; q < 8; q++) {
            float4 q0 = *(const float4*)&qs[q][l * 4];
            float4 q1 = *(const float4*)&qs[q][128 + l * 4];
            float acc = 0.f;
            acc = fmaf(tanha(base4[0].x + q0.x), W4[0].x, acc);
            acc = fmaf(tanha(base4[0].y + q0.y), W4[0].y, acc);
            acc = fmaf(tanha(base4[0].z + q0.z), W4[0].z, acc);
            acc = fmaf(tanha(base4[0].w + q0.w), W4[0].w, acc);
            acc = fmaf(tanha(base4[1].x + q1.x), W4[1].x, acc);
            acc = fmaf(tanha(base4[1].y + q1.y), W4[1].y, acc);
            acc = fmaf(tanha(base4[1].z + q1.z), W4[1].z, acc);
            acc = fmaf(tanha(base4[1].w + q1.w), W4[1].w, acc);
            a8[q] = acc;
        }
        float b4v[4];
        #pragma unroll
        for (int j = 0; j < 4; j++) {
            float keep = h16 ? a8[j + 4] : a8[j];
            float send = h16 ? a8[j] : a8[j + 4];
            b4v[j] = keep + __shfl_xor_sync(~0u, send, 16);
        }
        float c2v[2];
        #pragma unroll
        for (int j = 0; j < 2; j++) {
            float keep = h8 ? b4v[j + 2] : b4v[j];
            float send = h8 ? b4v[j] : b4v[j + 2];
            c2v[j] = keep + __shfl_xor_sync(~0u, send, 8);
        }
        float d1;
        {
            float keep = h4 ? c2v[1] : c2v[0];
            float send = h4 ? c2v[0] : c2v[1];
            d1 = keep + __shfl_xor_sync(~0u, send, 4);
        }
        d1 += __shfl_xor_sync(~0u, d1, 2);
        d1 += __shfl_xor_sync(~0u, d1, 1);
        if ((l & 3) == 0) {
            int m = mask[(p * NR + myq) * NK + k];
            g_logit[(p * NR + myq) * NK + k] = m ? NEGINF : d1;
        }
    }
}

// =====================================================================
// Kernel 8: greedy choose + log_softmax at chosen index.
// =====================================================================
__global__ __launch_bounds__(256)
void k_choose(float* __restrict__ out)
{
    __shared__ float ls[NK];
    __shared__ float rv[256];
    __shared__ int   ri[256];
    __shared__ float rs[256];
    const int b = blockIdx.x;
    const int t = threadIdx.x;

    float lm = NEGINF; int li = 0x7fffffff;
    for (int k = t; k < NK; k += 256) {
        float lg = g_logit[b * NK + k];
        float l  = (lg == NEGINF) ? NEGINF : tanhf(lg) * 10.0f;
        ls[k] = l;
        if (l > lm || (l == lm && k < li)) { lm = l; li = k; }
    }
    rv[t] = lm; ri[t] = li;
    __syncthreads();
    #pragma unroll
    for (int s = 128; s >= 32; s >>= 1) {
        if (t < s) {
            float v2 = rv[t + s]; int i2 = ri[t + s];
            if (v2 > rv[t] || (v2 == rv[t] && i2 < ri[t])) { rv[t] = v2; ri[t] = i2; }
        }
        __syncthreads();
    }
    if (t < 32) {
        float v = rv[t]; int i = ri[t];
        #pragma unroll
        for (int o = 16; o; o >>= 1) {
            float v2 = __shfl_xor_sync(~0u, v, o);
            int   i2 = __shfl_xor_sync(~0u, i, o);
            if (v2 > v || (v2 == v && i2 < i)) { v = v2; i = i2; }
        }
        if (t == 0) { rv[0] = v; ri[0] = i; }
    }
    __syncthreads();
    float maxv = rv[0]; int chosen = ri[0];

    float psum = 0.f;
    for (int k = t; k < NK; k += 256) psum += __expf(ls[k] - maxv);
    rs[t] = psum;
    __syncthreads();
    #pragma unroll
    for (int s = 128; s >= 32; s >>= 1) {
        if (t < s) rs[t] += rs[t + s];
        __syncthreads();
    }
    if (t == 0) {
        float s = 0.f;
        #pragma unroll
        for (int i = 0; i < 32; i++) s += rs[i];
        out[2 * BB * H + b] = ls[chosen] - maxv - __logf(s);
    }
}

// =====================================================================
// launch
// =====================================================================
extern "C" void kernel_launch(void* const* d_in, const int* in_sizes, int n_in,
                              void* d_out, int out_size)
{
    const float* X       = (const float*)d_in[0];
    const float* K       = (const float*)d_in[1];
    const float* V       = (const float*)d_in[2];
    const float* query   = (const float*)d_in[3];
    const float* state1  = (const float*)d_in[4];
    const float* state2  = (const float*)d_in[5];
    const float* varfeat = (const float*)d_in[6];
    const int*   mask    = (const int*)  d_in[7];
    const float* nnQ     = (const float*)d_in[8];
    const float* nnO     = (const float*)d_in[9];
    const float* nnA     = (const float*)d_in[10];
    const float* nnB     = (const float*)d_in[11];
    const float* nnW     = (const float*)d_in[12];
    const float* Wih     = (const float*)d_in[13];
    const float* Whh     = (const float*)d_in[14];
    const float* bih     = (const float*)d_in[15];
    const float* bhh     = (const float*)d_in[16];
    float* out = (float*)d_out;

    k_gates <<<dim3(8, 8, 2), 256>>>(query, state1, Wih, Whh);
    k_act_c <<<128, 256>>>(state2, bih, bhh, out);
    k_act_h <<<128, 256>>>(bih, bhh, out);
    k_qproj <<<dim3(4, 8, 4), 256>>>(out, nnQ);
    k_score <<<dim3(NP, HEADS), 256>>>(K, mask);
    k_av    <<<dim3(NP, HEADS), 256>>>(V);
    k_qm    <<<dim3(4, 8, 4), 256>>>(nnO);
    k_logit <<<dim3(8, NP), 256>>>(X, varfeat, nnA, nnB, nnW, mask);
    k_choose<<<BB, 256>>>(out);
}

// round 14
// speedup vs baseline: 1.1437x; 1.1437x over previous
#include <cuda_runtime.h>
#include <cuda_bf16.h>
#include <math.h>

#define NP 64
#define NR 8
#define NK 500
#define H 256
#define HEADS 8
#define VD 8
#define HD 32
#define BB (NP*NR)          // 512
#define NEGINF (__int_as_float(0xff800000))

// ---------------- scratch (device globals; no allocations allowed) ----------------
__device__ float g_gates [BB * 4 * H];    // 512 x 1024 (partial 0: query@Wih)
__device__ float g_gates2[BB * 4 * H];    // 512 x 1024 (partial 1: state1@Whh)
__device__ float g_xcat [BB * H];         // 512 x 256
__device__ float g_qp0  [BB * H];         // Q-proj k-split partials
__device__ float g_qp1  [BB * H];
__device__ float g_qp2  [BB * H];
__device__ float g_qp3  [BB * H];
__device__ float g_S    [HEADS * NP * NR * NK];  // softmax probs, 8MB
__device__ float g_qm0  [BB * H];         // qm k-split partials
__device__ float g_qm1  [BB * H];
__device__ float g_qm2  [BB * H];
__device__ float g_qm3  [BB * H];
__device__ float g_logit[BB * NK];        // 512 x 500

__device__ __forceinline__ float tanha(float x) {
    float y; asm("tanh.approx.f32 %0, %1;" : "=f"(y) : "f"(x)); return y;
}
__device__ __forceinline__ float sigm(float x) { return 1.0f / (1.0f + __expf(-x)); }

// =====================================================================
// Kernel 1: split-K gates GEMM. z=0: query@Wih^T, z=1: state1@Whh^T
// C[512,1024], K=256 per split. 64x64 tiles, 4x4 micro, double-buffered.
// (R11 version — measured in the 146us config)
// =====================================================================
__global__ __launch_bounds__(256)
void k_gates(const float* __restrict__ q, const float* __restrict__ s1,
             const float* __restrict__ Wih, const float* __restrict__ Whh)
{
    __shared__ float As[2][16][68];
    __shared__ float Bs[2][16][68];
    const int t  = threadIdx.x;
    const int tx = t & 15, ty = t >> 4;
    const int n0 = blockIdx.x * 64;
    const int m0 = blockIdx.y * 64;
    const int z  = blockIdx.z;
    const float* Ap = z ? s1  : q;
    const float* Wp = z ? Whh : Wih;

    float acc[4][4] = {};

    auto fetch = [&](int kt, int r, float& a, float& b) {
        int i = r * 256 + t;
        int mm = i >> 4, kx = i & 15;
        int kk = kt * 16;
        a = Ap[(m0 + mm) * 256 + kk + kx];
        b = Wp[(n0 + mm) * 256 + kk + kx];
    };

    #pragma unroll
    for (int r = 0; r < 4; r++) {
        float a, b; fetch(0, r, a, b);
        int i = r * 256 + t; int mm = i >> 4, kx = i & 15;
        As[0][kx][mm] = a; Bs[0][kx][mm] = b;
    }
    __syncthreads();

    int cur = 0;
    for (int kt = 0; kt < 16; kt++) {
        float pa[4], pb[4];
        if (kt < 15) {
            #pragma unroll
            for (int r = 0; r < 4; r++) fetch(kt + 1, r, pa[r], pb[r]);
        }
        #pragma unroll
        for (int k = 0; k < 16; k++) {
            float4 a4 = *(const float4*)&As[cur][k][ty * 4];
            float4 b4 = *(const float4*)&Bs[cur][k][tx * 4];
            float av[4] = {a4.x, a4.y, a4.z, a4.w};
            float bv[4] = {b4.x, b4.y, b4.z, b4.w};
            #pragma unroll
            for (int r = 0; r < 4; r++)
                #pragma unroll
                for (int c = 0; c < 4; c++)
                    acc[r][c] = fmaf(av[r], bv[c], acc[r][c]);
        }
        if (kt < 15) {
            int nxt = cur ^ 1;
            #pragma unroll
            for (int r = 0; r < 4; r++) {
                int i = r * 256 + t; int mm = i >> 4, kx = i & 15;
                As[nxt][kx][mm] = pa[r]; Bs[nxt][kx][mm] = pb[r];
            }
            __syncthreads();
            cur = nxt;
        }
    }
    float* dst = z ? g_gates2 : g_gates;
    #pragma unroll
    for (int r = 0; r < 4; r++) {
        int m = m0 + ty * 4 + r;
        #pragma unroll
        for (int c = 0; c < 4; c++) {
            int n = n0 + tx * 4 + c;
            dst[m * 1024 + n] = acc[r][c];
        }
    }
}

// =====================================================================
// Kernel 2: LSTM activations -> h, c  (merged, float4)
// =====================================================================
__global__ __launch_bounds__(256)
void k_act(const float* __restrict__ s2,
           const float* __restrict__ bih, const float* __restrict__ bhh,
           float* __restrict__ out)
{
    int idx4 = blockIdx.x * 256 + threadIdx.x;    // 0..32767 (float4 units)
    int b = idx4 >> 6, j4 = (idx4 & 63);
    const float4* g0 = (const float4*)(g_gates  + b * 1024);
    const float4* g1 = (const float4*)(g_gates2 + b * 1024);
    const float4* B0 = (const float4*)bih;
    const float4* B1 = (const float4*)bhh;

    float4 gi = g0[j4],      gf = g0[j4 + 64],  gg = g0[j4 + 128], go = g0[j4 + 192];
    float4 hi = g1[j4],      hf = g1[j4 + 64],  hg = g1[j4 + 128], ho = g1[j4 + 192];
    float4 bi = B0[j4],      bf = B0[j4 + 64],  bg = B0[j4 + 128], bo = B0[j4 + 192];
    float4 ci = B1[j4],      cf = B1[j4 + 64],  cg_ = B1[j4 + 128], co = B1[j4 + 192];
    float4 s4 = ((const float4*)s2)[idx4];

    float iv[4] = {gi.x+hi.x+bi.x+ci.x, gi.y+hi.y+bi.y+ci.y, gi.z+hi.z+bi.z+ci.z, gi.w+hi.w+bi.w+ci.w};
    float fv[4] = {gf.x+hf.x+bf.x+cf.x, gf.y+hf.y+bf.y+cf.y, gf.z+hf.z+bf.z+cf.z, gf.w+hf.w+bf.w+cf.w};
    float gv[4] = {gg.x+hg.x+bg.x+cg_.x, gg.y+hg.y+bg.y+cg_.y, gg.z+hg.z+bg.z+cg_.z, gg.w+hg.w+bg.w+cg_.w};
    float ov[4] = {go.x+ho.x+bo.x+co.x, go.y+ho.y+bo.y+co.y, go.z+ho.z+bo.z+co.z, go.w+ho.w+bo.w+co.w};
    float sv[4] = {s4.x, s4.y, s4.z, s4.w};

    float4 hout, cout;
    float* hp = (float*)&hout; float* cp = (float*)&cout;
    #pragma unroll
    for (int e = 0; e < 4; e++) {
        float c = sigm(fv[e]) * sv[e] + sigm(iv[e]) * tanhf(gv[e]);
        float h = sigm(ov[e]) * tanhf(c);
        hp[e] = h; cp[e] = c;
    }
    ((float4*)out)[idx4] = hout;
    ((float4*)out)[BB * H / 4 + idx4] = cout;
}

// =====================================================================
// Kernel 3: Q projection GEMM (512x256 @ 256x256), split-K 4.
// =====================================================================
__global__ __launch_bounds__(256)
void k_qproj(const float* __restrict__ hbuf, const float* __restrict__ nnQ)
{
    __shared__ float As[2][16][68];
    __shared__ float Bs[2][16][68];
    const int t  = threadIdx.x;
    const int tx = t & 15, ty = t >> 4;
    const int n0 = blockIdx.x * 64;
    const int m0 = blockIdx.y * 64;
    const int kb = blockIdx.z * 64;

    float acc[4][4] = {};

    auto fetchA = [&](int kt, int r, float& a) {
        int i = r * 256 + t;
        int mm = i >> 4, kx = i & 15;
        a = hbuf[(m0 + mm) * 256 + kb + kt * 16 + kx];
    };
    auto fetchB = [&](int kt, int r, float& b) {
        int i = r * 256 + t;
        int kx = i >> 6, nn = i & 63;
        int n = n0 + nn;
        b = nnQ[(n >> 5) * (H * HD) + (kb + kt * 16 + kx) * HD + (n & 31)];
    };

    #pragma unroll
    for (int r = 0; r < 4; r++) {
        float a, b; fetchA(0, r, a); fetchB(0, r, b);
        int i = r * 256 + t;
        As[0][i & 15][i >> 4] = a;
        Bs[0][i >> 6][i & 63] = b;
    }
    __syncthreads();

    int cur = 0;
    #pragma unroll
    for (int kt = 0; kt < 4; kt++) {
        float pa[4], pb[4];
        if (kt < 3) {
            #pragma unroll
            for (int r = 0; r < 4; r++) { fetchA(kt + 1, r, pa[r]); fetchB(kt + 1, r, pb[r]); }
        }
        #pragma unroll
        for (int k = 0; k < 16; k++) {
            float4 a4 = *(const float4*)&As[cur][k][ty * 4];
            float4 b4 = *(const float4*)&Bs[cur][k][tx * 4];
            float av[4] = {a4.x, a4.y, a4.z, a4.w};
            float bv[4] = {b4.x, b4.y, b4.z, b4.w};
            #pragma unroll
            for (int r = 0; r < 4; r++)
                #pragma unroll
                for (int c = 0; c < 4; c++)
                    acc[r][c] = fmaf(av[r], bv[c], acc[r][c]);
        }
        if (kt < 3) {
            int nxt = cur ^ 1;
            #pragma unroll
            for (int r = 0; r < 4; r++) {
                int i = r * 256 + t;
                As[nxt][i & 15][i >> 4] = pa[r];
                Bs[nxt][i >> 6][i & 63] = pb[r];
            }
            __syncthreads();
            cur = nxt;
        }
    }
    float* dst = (blockIdx.z == 0) ? g_qp0 : (blockIdx.z == 1) ? g_qp1
               : (blockIdx.z == 2) ? g_qp2 : g_qp3;
    #pragma unroll
    for (int r = 0; r < 4; r++) {
        int m = m0 + ty * 4 + r;
        #pragma unroll
        for (int c = 0; c < 4; c++)
            dst[m * 256 + n0 + tx * 4 + c] = acc[r][c];
    }
}

// =====================================================================
// Kernel 4: scores + softmax per (p, head). Writes probs to g_S.
// =====================================================================
struct SmemScore {
    float Qs[8][32];
    float Ss[8][512];
};

__global__ __launch_bounds__(256)
void k_score(const float* __restrict__ K, const int* __restrict__ mask)
{
    __shared__ SmemScore sm;
    const int p = blockIdx.x, a = blockIdx.y;
    const int t = threadIdx.x, w = t >> 5, l = t & 31;

    {
        int i = (p * NR + w) * 256 + a * HD + l;
        sm.Qs[w][l] = (g_qp0[i] + g_qp1[i] + g_qp2[i] + g_qp3[i]) * 0.17677669529663687f;
    }
    __syncthreads();

    const float* Kp = K + (size_t)(a * NP + p) * NK * HD;
    #pragma unroll
    for (int sweep = 0; sweep < 2; sweep++) {
        int k = sweep * 256 + t;
        if (k < NK) {
            float4 kr[8];
            const float4* kp4 = (const float4*)(Kp + k * HD);
            #pragma unroll
            for (int i = 0; i < 8; i++) kr[i] = kp4[i];
            #pragma unroll
            for (int q = 0; q < 8; q++) {
                const float4* q4 = (const float4*)sm.Qs[q];
                float acc = 0.f;
                #pragma unroll
                for (int i = 0; i < 8; i++) {
                    float4 qq = q4[i];
                    acc = fmaf(kr[i].x, qq.x, acc);
                    acc = fmaf(kr[i].y, qq.y, acc);
                    acc = fmaf(kr[i].z, qq.z, acc);
                    acc = fmaf(kr[i].w, qq.w, acc);
                }
                int m = mask[(p * NR + q) * NK + k];
                sm.Ss[q][k] = m ? NEGINF : acc;
            }
        }
    }
    __syncthreads();

    {
        float mx = NEGINF;
        for (int k = l; k < NK; k += 32) mx = fmaxf(mx, sm.Ss[w][k]);
        #pragma unroll
        for (int o = 16; o; o >>= 1) mx = fmaxf(mx, __shfl_xor_sync(~0u, mx, o));
        float sum = 0.f;
        for (int k = l; k < NK; k += 32) {
            float e = __expf(sm.Ss[w][k] - mx);
            sm.Ss[w][k] = e; sum += e;
        }
        #pragma unroll
        for (int o = 16; o; o >>= 1) sum += __shfl_xor_sync(~0u, sum, o);
        float inv = 1.f / sum;
        float* Sp = g_S + ((size_t)(a * NP + p) * NR + w) * NK;
        for (int k = l; k < NK; k += 32) Sp[k] = sm.Ss[w][k] * inv;
    }
}

// =====================================================================
// Kernel 5: x = S @ V per (p, head).
// =====================================================================
struct SmemAV {
    alignas(16) float xp[4][8][32];
    float Ss[8][504];
};

__global__ __launch_bounds__(256)
void k_av(const float* __restrict__ V)
{
    __shared__ SmemAV sm;
    const int p = blockIdx.x, a = blockIdx.y;
    const int t = threadIdx.x, w = t >> 5, l = t & 31;

    {
        const float* Sp = g_S + ((size_t)(a * NP + p) * NR + w) * NK;
        for (int k = l; k < NK; k += 32) sm.Ss[w][k] = Sp[k];
    }
    __syncthreads();

    const int q  = w;
    const int dg = l & 7;
    const int ks = l >> 3;
    const float4* Vp4 = (const float4*)(V + (size_t)(a * NP + p) * NK * HD);

    float4 acc = {0.f, 0.f, 0.f, 0.f};
    const int kbase = ks * 125;
    #pragma unroll 5
    for (int kk = 0; kk < 125; kk++) {
        int k = kbase + kk;
        float sv = sm.Ss[q][k];
        float4 v = Vp4[k * 8 + dg];
        acc.x = fmaf(sv, v.x, acc.x);
        acc.y = fmaf(sv, v.y, acc.y);
        acc.z = fmaf(sv, v.z, acc.z);
        acc.w = fmaf(sv, v.w, acc.w);
    }
    *(float4*)&sm.xp[ks][q][dg * 4] = acc;
    __syncthreads();

    {
        int q2 = t >> 5, d = t & 31;
        float s = sm.xp[0][q2][d] + sm.xp[1][q2][d] + sm.xp[2][q2][d] + sm.xp[3][q2][d];
        g_xcat[(p * NR + q2) * H + a * HD + d] = s;
    }
}

// =====================================================================
// Kernel 6: qm = x_cat @ nn_O, tiled GEMM, split-K 4.
// =====================================================================
__global__ __launch_bounds__(256)
void k_qm(const float* __restrict__ nnO)
{
    __shared__ float As[2][16][68];
    __shared__ float Bs[2][16][68];
    const int t  = threadIdx.x;
    const int tx = t & 15, ty = t >> 4;
    const int n0 = blockIdx.x * 64;
    const int m0 = blockIdx.y * 64;
    const int kb = blockIdx.z * 64;

    float acc[4][4] = {};

    auto fetchA = [&](int kt, int r, float& a) {
        int i = r * 256 + t;
        int mm = i >> 4, kx = i & 15;
        a = g_xcat[(m0 + mm) * 256 + kb + kt * 16 + kx];
    };
    auto fetchB = [&](int kt, int r, float& b) {
        int i = r * 256 + t;
        int kx = i >> 6, nn = i & 63;
        b = nnO[(kb + kt * 16 + kx) * 256 + n0 + nn];
    };

    #pragma unroll
    for (int r = 0; r < 4; r++) {
        float a, b; fetchA(0, r, a); fetchB(0, r, b);
        int i = r * 256 + t;
        As[0][i & 15][i >> 4] = a;
        Bs[0][i >> 6][i & 63] = b;
    }
    __syncthreads();

    int cur = 0;
    #pragma unroll
    for (int kt = 0; kt < 4; kt++) {
        float pa[4], pb[4];
        if (kt < 3) {
            #pragma unroll
            for (int r = 0; r < 4; r++) { fetchA(kt + 1, r, pa[r]); fetchB(kt + 1, r, pb[r]); }
        }
        #pragma unroll
        for (int k = 0; k < 16; k++) {
            float4 a4 = *(const float4*)&As[cur][k][ty * 4];
            float4 b4 = *(const float4*)&Bs[cur][k][tx * 4];
            float av[4] = {a4.x, a4.y, a4.z, a4.w};
            float bv[4] = {b4.x, b4.y, b4.z, b4.w};
            #pragma unroll
            for (int r = 0; r < 4; r++)
                #pragma unroll
                for (int c = 0; c < 4; c++)
                    acc[r][c] = fmaf(av[r], bv[c], acc[r][c]);
        }
        if (kt < 3) {
            int nxt = cur ^ 1;
            #pragma unroll
            for (int r = 0; r < 4; r++) {
                int i = r * 256 + t;
                As[nxt][i & 15][i >> 4] = pa[r];
                Bs[nxt][i >> 6][i & 63] = pb[r];
            }
            __syncthreads();
            cur = nxt;
        }
    }
    float* dst = (blockIdx.z == 0) ? g_qm0 : (blockIdx.z == 1) ? g_qm1
               : (blockIdx.z == 2) ? g_qm2 : g_qm3;
    #pragma unroll
    for (int r = 0; r < 4; r++) {
        int m = m0 + ty * 4 + r;
        #pragma unroll
        for (int c = 0; c < 4; c++)
            dst[m * 256 + n0 + tx * 4 + c] = acc[r][c];
    }
}

// =====================================================================
// Kernel 7: logits (R11 version). block = (p, ktile of 64).
// =====================================================================
__global__ __launch_bounds__(256)
void k_logit(const float* __restrict__ X, const float* __restrict__ varfeat,
             const float* __restrict__ nnA, const float* __restrict__ nnB,
             const float* __restrict__ nnW, const int* __restrict__ mask)
{
    __shared__ float qs[8][256];
    const int p = blockIdx.y, kt = blockIdx.x;
    const int t = threadIdx.x, w = t >> 5, l = t & 31;
    for (int i = t; i < 2048; i += 256)
        qs[i >> 8][i & 255] = g_qm0[p * 2048 + i] + g_qm1[p * 2048 + i]
                            + g_qm2[p * 2048 + i] + g_qm3[p * 2048 + i];

    float Ar[8][8], Wr[8], Br[8];
    #pragma unroll
    for (int i = 0; i < 8; i++) {
        int hh = l + 32 * i;
        Wr[i] = nnW[hh];
        Br[i] = nnB[hh];
        #pragma unroll
        for (int v = 0; v < 8; v++) Ar[v][i] = nnA[v * 256 + hh];
    }
    __syncthreads();

    const bool h16 = (l & 16), h8 = (l & 8), h4 = (l & 4);
    const int myq = (h16 ? 4 : 0) | (h8 ? 2 : 0) | (h4 ? 1 : 0);

    for (int it = 0; it < 8; it++) {
        int k = kt * 64 + it * 8 + w;
        if (k >= NK) continue;
        float vv[8];
        #pragma unroll
        for (int v = 0; v < 8; v++) vv[v] = __ldg(&varfeat[(p * VD + v) * NK + k]);
        const float* Xp = X + ((size_t)p * NK + k) * H;
        float base[8];
        #pragma unroll
        for (int i = 0; i < 8; i++) {
            float b = Xp[l + 32 * i] + Br[i];
            #pragma unroll
            for (int v = 0; v < 8; v++) b = fmaf(vv[v], Ar[v][i], b);
            base[i] = b;
        }
        float a8[8];
        #pragma unroll
        for (int q = 0; q < 8; q++) {
            float acc = 0.f;
            #pragma unroll
            for (int i = 0; i < 8; i++) {
                float tt = tanha(base[i] + qs[q][l + 32 * i]);
                acc = fmaf(tt, Wr[i], acc);
            }
            a8[q] = acc;
        }
        float b4v[4];
        #pragma unroll
        for (int j = 0; j < 4; j++) {
            float keep = h16 ? a8[j + 4] : a8[j];
            float send = h16 ? a8[j] : a8[j + 4];
            b4v[j] = keep + __shfl_xor_sync(~0u, send, 16);
        }
        float c2v[2];
        #pragma unroll
        for (int j = 0; j < 2; j++) {
            float keep = h8 ? b4v[j + 2] : b4v[j];
            float send = h8 ? b4v[j] : b4v[j + 2];
            c2v[j] = keep + __shfl_xor_sync(~0u, send, 8);
        }
        float d1;
        {
            float keep = h4 ? c2v[1] : c2v[0];
            float send = h4 ? c2v[0] : c2v[1];
            d1 = keep + __shfl_xor_sync(~0u, send, 4);
        }
        d1 += __shfl_xor_sync(~0u, d1, 2);
        d1 += __shfl_xor_sync(~0u, d1, 1);
        if ((l & 3) == 0) {
            int m = mask[(p * NR + myq) * NK + k];
            g_logit[(p * NR + myq) * NK + k] = m ? NEGINF : d1;
        }
    }
}

// =====================================================================
// Kernel 8: greedy choose + log_softmax at chosen index.
// =====================================================================
__global__ __launch_bounds__(256)
void k_choose(float* __restrict__ out)
{
    __shared__ float ls[NK];
    __shared__ float rv[256];
    __shared__ int   ri[256];
    __shared__ float rs[256];
    const int b = blockIdx.x;
    const int t = threadIdx.x;

    float lm = NEGINF; int li = 0x7fffffff;
    for (int k = t; k < NK; k += 256) {
        float lg = g_logit[b * NK + k];
        float l  = (lg == NEGINF) ? NEGINF : tanhf(lg) * 10.0f;
        ls[k] = l;
        if (l > lm || (l == lm && k < li)) { lm = l; li = k; }
    }
    rv[t] = lm; ri[t] = li;
    __syncthreads();
    #pragma unroll
    for (int s = 128; s >= 32; s >>= 1) {
        if (t < s) {
            float v2 = rv[t + s]; int i2 = ri[t + s];
            if (v2 > rv[t] || (v2 == rv[t] && i2 < ri[t])) { rv[t] = v2; ri[t] = i2; }
        }
        __syncthreads();
    }
    if (t < 32) {
        float v = rv[t]; int i = ri[t];
        #pragma unroll
        for (int o = 16; o; o >>= 1) {
            float v2 = __shfl_xor_sync(~0u, v, o);
            int   i2 = __shfl_xor_sync(~0u, i, o);
            if (v2 > v || (v2 == v && i2 < i)) { v = v2; i = i2; }
        }
        if (t == 0) { rv[0] = v; ri[0] = i; }
    }
    __syncthreads();
    float maxv = rv[0]; int chosen = ri[0];

    float psum = 0.f;
    for (int k = t; k < NK; k += 256) psum += __expf(ls[k] - maxv);
    rs[t] = psum;
    __syncthreads();
    #pragma unroll
    for (int s = 128; s >= 32; s >>= 1) {
        if (t < s) rs[t] += rs[t + s];
        __syncthreads();
    }
    if (t == 0) {
        float s = 0.f;
        #pragma unroll
        for (int i = 0; i < 32; i++) s += rs[i];
        out[2 * BB * H + b] = ls[chosen] - maxv - __logf(s);
    }
}

// =====================================================================
// launch
// =====================================================================
extern "C" void kernel_launch(void* const* d_in, const int* in_sizes, int n_in,
                              void* d_out, int out_size)
{
    const float* X       = (const float*)d_in[0];
    const float* K       = (const float*)d_in[1];
    const float* V       = (const float*)d_in[2];
    const float* query   = (const float*)d_in[3];
    const float* state1  = (const float*)d_in[4];
    const float* state2  = (const float*)d_in[5];
    const float* varfeat = (const float*)d_in[6];
    const int*   mask    = (const int*)  d_in[7];
    const float* nnQ     = (const float*)d_in[8];
    const float* nnO     = (const float*)d_in[9];
    const float* nnA     = (const float*)d_in[10];
    const float* nnB     = (const float*)d_in[11];
    const float* nnW     = (const float*)d_in[12];
    const float* Wih     = (const float*)d_in[13];
    const float* Whh     = (const float*)d_in[14];
    const float* bih     = (const float*)d_in[15];
    const float* bhh     = (const float*)d_in[16];
    float* out = (float*)d_out;

    k_gates <<<dim3(16, 8, 2), 256>>>(query, state1, Wih, Whh);
    k_act   <<<128, 256>>>(state2, bih, bhh, out);
    k_qproj <<<dim3(4, 8, 4), 256>>>(out, nnQ);
    k_score <<<dim3(NP, HEADS), 256>>>(K, mask);
    k_av    <<<dim3(NP, HEADS), 256>>>(V);
    k_qm    <<<dim3(4, 8, 4), 256>>>(nnO);
    k_logit <<<dim3(8, NP), 256>>>(X, varfeat, nnA, nnB, nnW, mask);
    k_choose<<<BB, 256>>>(out);
}